// round 5
// baseline (speedup 1.0000x reference)
#include <cuda_runtime.h>
#include <cuda_bf16.h>
#include <cstdint>
#include <math.h>

// ---------------------------------------------------------------------------
// Binary CNN fully fused.
//  - conv1 + BN: computed in DOUBLE precision (order-neutral "true" values);
//    sign decisions then match any faithful fp32 reference except within its
//    own ~1e-7 rounding band of zero.
//  - conv2/3/4: XNOR+POPC exact integers; sign via per-channel INTEGER
//    thresholds (reference fp32 BN chain is provably threshold-robust:
//    pre-activations are even integers, |v| at lattice >= ~0.5*|inv|).
//  - fc: exact integer dot + bias.
// ---------------------------------------------------------------------------

#define EPSBN 1e-5

// preprocessed weights / params
__device__ float    g_w1s[32 * 9];            // sign(w1) as +-1.0f
__device__ double   g_inv1d[32], g_bz1d[32];  // BN scale / shift (double, true)
__device__ double   g_b1d[32];                // conv1 bias (double)
__device__ unsigned g_wb2[64 * 3];            // [c*3+t], bit i = cin i
__device__ int      g_mu2[64],  g_T2[64];     // bit = (mu*d >= T)
__device__ unsigned g_wb3[128 * 3 * 2];       // [(c*3+t)*2+j], bit i = cin j*32+i
__device__ int      g_mu3[128], g_T3[128];
__device__ unsigned g_wb4[128 * 6 * 4];       // [(c*6+h)*4+j]
__device__ int      g_mu4[128], g_T4[128];
__device__ unsigned g_wfb[10 * 64];           // [o*64+jw], bit i = k jw*32+i (k=c*16+w)

// Reference fp32 BN chain on an integer pre-activation d (threshold-robust,
// any faithful variant gives the same integer thresholds):
__device__ __forceinline__ float bnref(float dv, float bias, float inv, float bz) {
    return __fadd_rn(__fmul_rn(__fadd_rn(dv, bias), inv), bz);
}

// Find integer threshold: bit(d) = (mu*d >= T) matching (bnref(d) >= 0)
// for all integers d in [-1025, 1025] (chain weakly monotone in d).
__device__ void mk_threshold(float b, float g, float be, float m, float v,
                             int* mu_out, int* T_out)
{
    float inv = __fmul_rn(g, rsqrtf(__fadd_rn(v, 1e-5f)));
    float bz  = __fsub_rn(be, __fmul_rn(m, inv));

    if (inv > 0.0f) {
        int lo = -1025, hi = 1025, ans = 1 << 20;
        while (lo <= hi) {
            int mid = lo + ((hi - lo) >> 1);
            if (bnref((float)mid, b, inv, bz) >= 0.0f) { ans = mid; hi = mid - 1; }
            else lo = mid + 1;
        }
        *mu_out = 1; *T_out = ans;
    } else if (inv < 0.0f) {
        int lo = -1025, hi = 1025, ans = -(1 << 20);
        while (lo <= hi) {
            int mid = lo + ((hi - lo) >> 1);
            if (bnref((float)mid, b, inv, bz) >= 0.0f) { ans = mid; lo = mid + 1; }
            else hi = mid - 1;
        }
        *mu_out = -1; *T_out = -ans;
    } else {
        *mu_out = 0; *T_out = (bz >= 0.0f) ? -(1 << 20) : (1 << 20);
    }
}

__global__ void prep_kernel(
    const float* __restrict__ w1, const float* __restrict__ b1,
    const float* __restrict__ w2, const float* __restrict__ b2,
    const float* __restrict__ w3, const float* __restrict__ b3,
    const float* __restrict__ w4, const float* __restrict__ b4,
    const float* __restrict__ g1, const float* __restrict__ be1,
    const float* __restrict__ m1, const float* __restrict__ v1,
    const float* __restrict__ g2, const float* __restrict__ be2,
    const float* __restrict__ m2, const float* __restrict__ v2,
    const float* __restrict__ g3, const float* __restrict__ be3,
    const float* __restrict__ m3, const float* __restrict__ v3,
    const float* __restrict__ g4, const float* __restrict__ be4,
    const float* __restrict__ m4, const float* __restrict__ v4,
    const float* __restrict__ wf)
{
    int u = blockIdx.x * blockDim.x + threadIdx.x;

    if (u < 288) {                       // sign(w1) as +-1.0f
        g_w1s[u] = (w1[u] >= 0.f) ? 1.f : -1.f;
        return;
    }
    u -= 288;
    if (u < 32) {                        // layer-1 BN params in DOUBLE (true values)
        int c = u;
        double inv = (double)g1[c] / sqrt((double)v1[c] + EPSBN);
        g_inv1d[c] = inv;
        g_bz1d[c]  = (double)be1[c] - (double)m1[c] * inv;
        g_b1d[c]   = (double)b1[c];
        return;
    }
    u -= 32;
    if (u < 320) {                       // integer thresholds, layers 2..4
        if (u < 64)       mk_threshold(b2[u], g2[u], be2[u], m2[u], v2[u],
                                       &g_mu2[u], &g_T2[u]);
        else if (u < 192) { int c = u - 64;
                          mk_threshold(b3[c], g3[c], be3[c], m3[c], v3[c],
                                       &g_mu3[c], &g_T3[c]); }
        else              { int c = u - 192;
                          mk_threshold(b4[c], g4[c], be4[c], m4[c], v4[c],
                                       &g_mu4[c], &g_T4[c]); }
        return;
    }
    u -= 320;
    if (u < 192) {                       // wb2: w2 (64,32,1,3)
        int c = u / 3, t = u % 3;
        unsigned word = 0;
        for (int i = 0; i < 32; i++)
            word |= (unsigned)(w2[c * 96 + i * 3 + t] >= 0.f) << i;
        g_wb2[u] = word;
        return;
    }
    u -= 192;
    if (u < 768) {                       // wb3: w3 (128,64,1,3)
        int c = u / 6, r = u % 6, t = r >> 1, j = r & 1;
        unsigned word = 0;
        for (int i = 0; i < 32; i++) {
            int cin = j * 32 + i;
            word |= (unsigned)(w3[c * 192 + cin * 3 + t] >= 0.f) << i;
        }
        g_wb3[u] = word;
        return;
    }
    u -= 768;
    if (u < 3072) {                      // wb4: w4 (128,128,6,1)
        int c = u / 24, r = u % 24, h = r >> 2, j = r & 3;
        unsigned word = 0;
        for (int i = 0; i < 32; i++) {
            int cin = j * 32 + i;
            word |= (unsigned)(w4[c * 768 + cin * 6 + h] >= 0.f) << i;
        }
        g_wb4[u] = word;
        return;
    }
    u -= 3072;
    if (u < 640) {                       // wfb: wf (10,2048), k = c*16+w
        int o = u / 64, jw = u % 64;
        unsigned word = 0;
        for (int i = 0; i < 32; i++)
            word |= (unsigned)(wf[o * 2048 + jw * 32 + i] >= 0.f) << i;
        g_wfb[u] = word;
    }
}

// ---------------------------------------------------------------------------
// Main fused kernel: 1 block = 1 sample, 128 threads (4 warps).
// ---------------------------------------------------------------------------
__global__ __launch_bounds__(128)
void bcnn_kernel(const float* __restrict__ x, const float* __restrict__ bf,
                 float* __restrict__ out)
{
    const int b   = blockIdx.x;
    const int tid = threadIdx.x;
    const int W   = tid >> 5;     // warp id
    const int L   = tid & 31;     // lane id

    __shared__ float    xs[768];       // input sample [6][128]
    __shared__ unsigned b1s[192];      // block1 bits: [h*32+w], bit c (32 ch)
    __shared__ unsigned b2s[384];      // block2 bits: [(h*32+w)*2+q] (64 ch)
    __shared__ unsigned b3s[384];      // block3 bits: [(h*16+wp)*4+q] (128 ch)
    __shared__ unsigned masks[128];    // conv4 sign bits per channel (16 w bits)
    __shared__ unsigned fcb[64];       // fc input bits, k = c*16+w

    // load sample
    const float* xb = x + (size_t)b * 768;
    for (int i = tid; i < 768; i += 128) xs[i] = xb[i];

    // ---- stage A: conv1 (real x, +-1 w) + bias + bn + pool(w2) + binarize ----
    // DOUBLE-precision accumulation + epilogue: order-neutral true values.
    double wrd[9];
#pragma unroll
    for (int t = 0; t < 9; t++) wrd[t] = (double)g_w1s[L * 9 + t];
    double inv1 = g_inv1d[L], bz1 = g_bz1d[L], bb1 = g_b1d[L];
    __syncthreads();

    for (int pos = W; pos < 192; pos += 4) {
        int h = pos >> 5, wp = pos & 31;
        const float* row = xs + h * 128;
        int base = 4 * wp - 4;
        double xv[11];
#pragma unroll
        for (int j = 0; j < 11; j++) {
            int col = base + j;
            xv[j] = (col >= 0 && col < 128) ? (double)row[col] : 0.0;
        }
        double s0 = 0.0, s1 = 0.0;
#pragma unroll
        for (int t = 0; t < 9; t++) {
            s0 = fma(wrd[t], xv[t],     s0);
            s1 = fma(wrd[t], xv[t + 2], s1);
        }
        double y0 = (s0 + bb1) * inv1 + bz1;
        double y1 = (s1 + bb1) * inv1 + bz1;
        unsigned word = __ballot_sync(0xffffffffu, (y0 >= 0.0) || (y1 >= 0.0));
        if (L == 0) b1s[pos] = word;
    }
    __syncthreads();

    // ---- stage B: conv2 (64ch, cin 32, kw 3, pad 1): integer threshold ----
    {
        int q = W & 1;                 // channel half, c = q*32 + L
        int c = q * 32 + L;
        unsigned wt0 = g_wb2[c * 3 + 0];
        unsigned wt1 = g_wb2[c * 3 + 1];
        unsigned wt2 = g_wb2[c * 3 + 2];
        int mu = g_mu2[c], T = g_T2[c];
        for (int pos = (W >> 1); pos < 192; pos += 2) {
            int w = pos & 31;
            int s = __popc(b1s[pos] ^ wt1);
            int nv = 1;
            if (w > 0)  { s += __popc(b1s[pos - 1] ^ wt0); nv++; }
            if (w < 31) { s += __popc(b1s[pos + 1] ^ wt2); nv++; }
            int d = 32 * nv - 2 * s;
            unsigned word = __ballot_sync(0xffffffffu, mu * d >= T);
            if (L == 0) b2s[pos * 2 + q] = word;
        }
    }
    __syncthreads();

    // ---- stage C: conv3 (128ch, cin 64, kw 3, pad 1) + pool(w2) ----
    {
        int c = tid;                   // warp W owns channels 32W..32W+31
        unsigned w3r[3][2];
#pragma unroll
        for (int t = 0; t < 3; t++)
#pragma unroll
            for (int j = 0; j < 2; j++) w3r[t][j] = g_wb3[(c * 3 + t) * 2 + j];
        int mu = g_mu3[c], T = g_T3[c];

        for (int pp = 0; pp < 96; pp++) {
            int h = pp >> 4, wp = pp & 15;
            int pbase = (h * 32 + 2 * wp) * 2;
            unsigned A1_0 = b2s[pbase],     A1_1 = b2s[pbase + 1];
            unsigned A2_0 = b2s[pbase + 2], A2_1 = b2s[pbase + 3];
            // w0 = 2wp: taps (A0,A1,A2); w1 = 2wp+1: taps (A1,A2,A3)
            int s0 = __popc(A1_0 ^ w3r[1][0]) + __popc(A1_1 ^ w3r[1][1])
                   + __popc(A2_0 ^ w3r[2][0]) + __popc(A2_1 ^ w3r[2][1]);
            int nv0 = 2;
            if (wp > 0) {
                unsigned A0_0 = b2s[pbase - 2], A0_1 = b2s[pbase - 1];
                s0 += __popc(A0_0 ^ w3r[0][0]) + __popc(A0_1 ^ w3r[0][1]);
                nv0 = 3;
            }
            int s1 = __popc(A1_0 ^ w3r[0][0]) + __popc(A1_1 ^ w3r[0][1])
                   + __popc(A2_0 ^ w3r[1][0]) + __popc(A2_1 ^ w3r[1][1]);
            int nv1 = 2;
            if (wp < 15) {
                unsigned A3_0 = b2s[pbase + 4], A3_1 = b2s[pbase + 5];
                s1 += __popc(A3_0 ^ w3r[2][0]) + __popc(A3_1 ^ w3r[2][1]);
                nv1 = 3;
            }
            int e0 = mu * (64 * nv0 - 2 * s0);
            int e1 = mu * (64 * nv1 - 2 * s1);
            unsigned word = __ballot_sync(0xffffffffu, max(e0, e1) >= T);
            if (L == 0) b3s[pp * 4 + W] = word;
        }
    }
    __syncthreads();

    // ---- stage D: conv4 (128ch, cin 128, kh 6, no pad) ----
    {
        int c = tid;
        unsigned w4r[24];
#pragma unroll
        for (int k = 0; k < 24; k++) w4r[k] = g_wb4[c * 24 + k];
        int mu = g_mu4[c], T = g_T4[c];
        unsigned mask = 0;
        for (int w = 0; w < 16; w++) {
            int s = 0;
#pragma unroll
            for (int h = 0; h < 6; h++)
#pragma unroll
                for (int j = 0; j < 4; j++)
                    s += __popc(b3s[(h * 16 + w) * 4 + j] ^ w4r[h * 4 + j]);
            int d = 768 - 2 * s;
            mask |= (mu * d >= T) ? (1u << w) : 0u;
        }
        masks[c] = mask;
    }
    __syncthreads();
    // repack to fc bit order: k = c*16 + w; word j = masks[2j] | masks[2j+1]<<16
    if (tid < 64) fcb[tid] = masks[2 * tid] | (masks[2 * tid + 1] << 16);
    __syncthreads();

    // ---- stage E: fc (10 x 2048 binary dot) + bf (exact integer) ----
    for (int o = W; o < 10; o += 4) {
        int s = __popc(fcb[L]      ^ g_wfb[o * 64 + L])
              + __popc(fcb[L + 32] ^ g_wfb[o * 64 + 32 + L]);
        int tot = __reduce_add_sync(0xffffffffu, s);
        if (L == 0) out[(size_t)b * 10 + o] = (float)(2048 - 2 * tot) + bf[o];
    }
}

extern "C" void kernel_launch(void* const* d_in, const int* in_sizes, int n_in,
                              void* d_out, int out_size)
{
    const float* x   = (const float*)d_in[0];
    const float* w1  = (const float*)d_in[1];
    const float* b1  = (const float*)d_in[2];
    const float* w2  = (const float*)d_in[3];
    const float* b2  = (const float*)d_in[4];
    const float* w3  = (const float*)d_in[5];
    const float* b3  = (const float*)d_in[6];
    const float* w4  = (const float*)d_in[7];
    const float* b4  = (const float*)d_in[8];
    const float* g1  = (const float*)d_in[9];
    const float* be1 = (const float*)d_in[10];
    const float* m1  = (const float*)d_in[11];
    const float* v1  = (const float*)d_in[12];
    const float* g2  = (const float*)d_in[13];
    const float* be2 = (const float*)d_in[14];
    const float* m2  = (const float*)d_in[15];
    const float* v2  = (const float*)d_in[16];
    const float* g3  = (const float*)d_in[17];
    const float* be3 = (const float*)d_in[18];
    const float* m3  = (const float*)d_in[19];
    const float* v3  = (const float*)d_in[20];
    const float* g4  = (const float*)d_in[21];
    const float* be4 = (const float*)d_in[22];
    const float* m4  = (const float*)d_in[23];
    const float* v4  = (const float*)d_in[24];
    const float* wf  = (const float*)d_in[25];
    const float* bf  = (const float*)d_in[26];

    int B = in_sizes[0] / 768;

    prep_kernel<<<21, 256>>>(w1, b1, w2, b2, w3, b3, w4, b4,
                             g1, be1, m1, v1, g2, be2, m2, v2,
                             g3, be3, m3, v3, g4, be4, m4, v4, wf);
    bcnn_kernel<<<B, 128>>>(x, bf, (float*)d_out);
}

// round 6
// speedup vs baseline: 9.0177x; 9.0177x over previous
#include <cuda_runtime.h>
#include <cuda_bf16.h>
#include <cstdint>
#include <math.h>

// ---------------------------------------------------------------------------
// Binary CNN fully fused.
//  - conv1 + BN: fp32 fast path (FFMA chain, folded epilogue); positions with
//    |y| < BAND (~0.1%) fall back to the exact double chain that measured
//    rel_err == 0.0 in round 5. Deterministic, bit-identical to round 5.
//  - conv2/3/4: XNOR+POPC exact integers; per-channel INTEGER thresholds.
//  - fc: exact integer dot + bias.
// ---------------------------------------------------------------------------

#define EPSBND 1e-5
#define BAND   1e-3f

// preprocessed weights / params
__device__ float    g_w1s[32 * 9];            // sign(w1) as +-1.0f
__device__ double   g_inv1d[32], g_bz1d[32];  // exact BN params (double)
__device__ double   g_b1d[32];                // conv1 bias (double)
__device__ float    g_inv1f[32], g_off1f[32]; // fp32 fast path: y=fma(s,inv,off)
__device__ unsigned g_wb2[64 * 3];            // [c*3+t], bit i = cin i
__device__ int      g_mu2[64],  g_T2[64];     // bit = (mu*d >= T)
__device__ unsigned g_wb3[128 * 3 * 2];       // [(c*3+t)*2+j], bit i = cin j*32+i
__device__ int      g_mu3[128], g_T3[128];
__device__ unsigned g_wb4[128 * 6 * 4];       // [(c*6+h)*4+j]
__device__ int      g_mu4[128], g_T4[128];
__device__ unsigned g_wfb[10 * 64];           // [o*64+jw], bit i = k jw*32+i (k=c*16+w)

__device__ __forceinline__ float bnref(float dv, float bias, float inv, float bz) {
    return __fadd_rn(__fmul_rn(__fadd_rn(dv, bias), inv), bz);
}

// Integer threshold: bit(d) = (mu*d >= T) matching (bnref(d) >= 0),
// d in [-1025, 1025], chain weakly monotone in d.
__device__ void mk_threshold(float b, float g, float be, float m, float v,
                             int* mu_out, int* T_out)
{
    float inv = __fmul_rn(g, rsqrtf(__fadd_rn(v, 1e-5f)));
    float bz  = __fsub_rn(be, __fmul_rn(m, inv));

    if (inv > 0.0f) {
        int lo = -1025, hi = 1025, ans = 1 << 20;
        while (lo <= hi) {
            int mid = lo + ((hi - lo) >> 1);
            if (bnref((float)mid, b, inv, bz) >= 0.0f) { ans = mid; hi = mid - 1; }
            else lo = mid + 1;
        }
        *mu_out = 1; *T_out = ans;
    } else if (inv < 0.0f) {
        int lo = -1025, hi = 1025, ans = -(1 << 20);
        while (lo <= hi) {
            int mid = lo + ((hi - lo) >> 1);
            if (bnref((float)mid, b, inv, bz) >= 0.0f) { ans = mid; lo = mid + 1; }
            else hi = mid - 1;
        }
        *mu_out = -1; *T_out = -ans;
    } else {
        *mu_out = 0; *T_out = (bz >= 0.0f) ? -(1 << 20) : (1 << 20);
    }
}

__global__ void prep_kernel(
    const float* __restrict__ w1, const float* __restrict__ b1,
    const float* __restrict__ w2, const float* __restrict__ b2,
    const float* __restrict__ w3, const float* __restrict__ b3,
    const float* __restrict__ w4, const float* __restrict__ b4,
    const float* __restrict__ g1, const float* __restrict__ be1,
    const float* __restrict__ m1, const float* __restrict__ v1,
    const float* __restrict__ g2, const float* __restrict__ be2,
    const float* __restrict__ m2, const float* __restrict__ v2,
    const float* __restrict__ g3, const float* __restrict__ be3,
    const float* __restrict__ m3, const float* __restrict__ v3,
    const float* __restrict__ g4, const float* __restrict__ be4,
    const float* __restrict__ m4, const float* __restrict__ v4,
    const float* __restrict__ wf)
{
    int u = blockIdx.x * blockDim.x + threadIdx.x;

    if (u < 288) {                       // sign(w1) as +-1.0f
        g_w1s[u] = (w1[u] >= 0.f) ? 1.f : -1.f;
        return;
    }
    u -= 288;
    if (u < 32) {                        // layer-1 BN params (double + fp32 fold)
        int c = u;
        double inv = (double)g1[c] / sqrt((double)v1[c] + EPSBND);
        double bz  = (double)be1[c] - (double)m1[c] * inv;
        g_inv1d[c] = inv;
        g_bz1d[c]  = bz;
        g_b1d[c]   = (double)b1[c];
        g_inv1f[c] = (float)inv;
        g_off1f[c] = (float)((double)b1[c] * inv + bz);
        return;
    }
    u -= 32;
    if (u < 320) {                       // integer thresholds, layers 2..4
        if (u < 64)       mk_threshold(b2[u], g2[u], be2[u], m2[u], v2[u],
                                       &g_mu2[u], &g_T2[u]);
        else if (u < 192) { int c = u - 64;
                          mk_threshold(b3[c], g3[c], be3[c], m3[c], v3[c],
                                       &g_mu3[c], &g_T3[c]); }
        else              { int c = u - 192;
                          mk_threshold(b4[c], g4[c], be4[c], m4[c], v4[c],
                                       &g_mu4[c], &g_T4[c]); }
        return;
    }
    u -= 320;
    if (u < 192) {                       // wb2: w2 (64,32,1,3)
        int c = u / 3, t = u % 3;
        unsigned word = 0;
        for (int i = 0; i < 32; i++)
            word |= (unsigned)(w2[c * 96 + i * 3 + t] >= 0.f) << i;
        g_wb2[u] = word;
        return;
    }
    u -= 192;
    if (u < 768) {                       // wb3: w3 (128,64,1,3)
        int c = u / 6, r = u % 6, t = r >> 1, j = r & 1;
        unsigned word = 0;
        for (int i = 0; i < 32; i++) {
            int cin = j * 32 + i;
            word |= (unsigned)(w3[c * 192 + cin * 3 + t] >= 0.f) << i;
        }
        g_wb3[u] = word;
        return;
    }
    u -= 768;
    if (u < 3072) {                      // wb4: w4 (128,128,6,1)
        int c = u / 24, r = u % 24, h = r >> 2, j = r & 3;
        unsigned word = 0;
        for (int i = 0; i < 32; i++) {
            int cin = j * 32 + i;
            word |= (unsigned)(w4[c * 768 + cin * 6 + h] >= 0.f) << i;
        }
        g_wb4[u] = word;
        return;
    }
    u -= 3072;
    if (u < 640) {                       // wfb: wf (10,2048), k = c*16+w
        int o = u / 64, jw = u % 64;
        unsigned word = 0;
        for (int i = 0; i < 32; i++)
            word |= (unsigned)(wf[o * 2048 + jw * 32 + i] >= 0.f) << i;
        g_wfb[u] = word;
    }
}

// ---------------------------------------------------------------------------
// Main fused kernel: 1 block = 1 sample, 128 threads (4 warps).
// ---------------------------------------------------------------------------
__global__ __launch_bounds__(128)
void bcnn_kernel(const float* __restrict__ x, const float* __restrict__ bf,
                 float* __restrict__ out)
{
    const int b   = blockIdx.x;
    const int tid = threadIdx.x;
    const int W   = tid >> 5;     // warp id
    const int L   = tid & 31;     // lane id

    __shared__ float    xs[6 * 136];   // padded sample rows: [6][4 | 128 | 4]
    __shared__ unsigned b1s[192];      // block1 bits: [h*32+w], bit c (32 ch)
    __shared__ unsigned b2s[384];      // block2 bits: [(h*32+w)*2+q] (64 ch)
    __shared__ unsigned b3s[384];      // block3 bits: [(h*16+wp)*4+q] (128 ch)
    __shared__ unsigned masks[128];    // conv4 sign bits per channel (16 w bits)
    __shared__ unsigned fcb[64];       // fc input bits, k = c*16+w

    // load sample with zero padding (4 cols each side)
    const float* xb = x + (size_t)b * 768;
    for (int i = tid; i < 768; i += 128) {
        int r = i >> 7, c = i & 127;
        xs[r * 136 + 4 + c] = xb[i];
    }
    if (tid < 48) {                    // 6 rows x 8 pad cells
        int r = tid >> 3, j = tid & 7;
        xs[r * 136 + ((j < 4) ? j : (j + 128))] = 0.f;
    }

    // ---- stage A: conv1 (real x, +-1 w) + bias + bn + pool(w2) + binarize ----
    // fp32 fast path; |y| < BAND falls back to exact double chain (round-5).
    float wrf[9];
#pragma unroll
    for (int t = 0; t < 9; t++) wrf[t] = g_w1s[L * 9 + t];
    float invf = g_inv1f[L], offf = g_off1f[L];
    __syncthreads();

    for (int pos = W; pos < 192; pos += 4) {
        int h = pos >> 5, wp = pos & 31;
        const float* row = xs + h * 136 + 4 * wp;  // col -4 of output wp maps to row[0]
        float xv[11];
#pragma unroll
        for (int j = 0; j < 11; j++) xv[j] = row[j];
        float s0 = 0.f, s1 = 0.f;
#pragma unroll
        for (int t = 0; t < 9; t++) {
            s0 = __fmaf_rn(wrf[t], xv[t],     s0);
            s1 = __fmaf_rn(wrf[t], xv[t + 2], s1);
        }
        float ym = fmaxf(__fmaf_rn(s0, invf, offf), __fmaf_rn(s1, invf, offf));
        bool bit;
        if (fabsf(ym) >= BAND) {
            bit = (ym >= 0.f);
        } else {                        // rare exact fallback (double, round-5 chain)
            double inv1 = g_inv1d[L], bz1 = g_bz1d[L], bb1 = g_b1d[L];
            double s0d = 0.0, s1d = 0.0;
#pragma unroll
            for (int t = 0; t < 9; t++) {
                s0d = fma((double)wrf[t], (double)xv[t],     s0d);
                s1d = fma((double)wrf[t], (double)xv[t + 2], s1d);
            }
            double y0 = (s0d + bb1) * inv1 + bz1;
            double y1 = (s1d + bb1) * inv1 + bz1;
            bit = (y0 >= 0.0) || (y1 >= 0.0);
        }
        unsigned word = __ballot_sync(0xffffffffu, bit);
        if (L == 0) b1s[pos] = word;
    }
    __syncthreads();

    // ---- stage B: conv2 (64ch, cin 32, kw 3, pad 1): integer threshold ----
    {
        int q = W & 1;                 // channel half, c = q*32 + L
        int c = q * 32 + L;
        unsigned wt0 = g_wb2[c * 3 + 0];
        unsigned wt1 = g_wb2[c * 3 + 1];
        unsigned wt2 = g_wb2[c * 3 + 2];
        int mu = g_mu2[c], T = g_T2[c];
        for (int pos = (W >> 1); pos < 192; pos += 2) {
            int w = pos & 31;
            int s = __popc(b1s[pos] ^ wt1);
            int nv = 1;
            if (w > 0)  { s += __popc(b1s[pos - 1] ^ wt0); nv++; }
            if (w < 31) { s += __popc(b1s[pos + 1] ^ wt2); nv++; }
            int d = 32 * nv - 2 * s;
            unsigned word = __ballot_sync(0xffffffffu, mu * d >= T);
            if (L == 0) b2s[pos * 2 + q] = word;
        }
    }
    __syncthreads();

    // ---- stage C: conv3 (128ch, cin 64, kw 3, pad 1) + pool(w2) ----
    {
        int c = tid;                   // warp W owns channels 32W..32W+31
        unsigned w3r[3][2];
#pragma unroll
        for (int t = 0; t < 3; t++)
#pragma unroll
            for (int j = 0; j < 2; j++) w3r[t][j] = g_wb3[(c * 3 + t) * 2 + j];
        int mu = g_mu3[c], T = g_T3[c];

        for (int pp = 0; pp < 96; pp++) {
            int h = pp >> 4, wp = pp & 15;
            int pbase = (h * 32 + 2 * wp) * 2;
            unsigned A1_0 = b2s[pbase],     A1_1 = b2s[pbase + 1];
            unsigned A2_0 = b2s[pbase + 2], A2_1 = b2s[pbase + 3];
            int s0 = __popc(A1_0 ^ w3r[1][0]) + __popc(A1_1 ^ w3r[1][1])
                   + __popc(A2_0 ^ w3r[2][0]) + __popc(A2_1 ^ w3r[2][1]);
            int nv0 = 2;
            if (wp > 0) {
                unsigned A0_0 = b2s[pbase - 2], A0_1 = b2s[pbase - 1];
                s0 += __popc(A0_0 ^ w3r[0][0]) + __popc(A0_1 ^ w3r[0][1]);
                nv0 = 3;
            }
            int s1 = __popc(A1_0 ^ w3r[0][0]) + __popc(A1_1 ^ w3r[0][1])
                   + __popc(A2_0 ^ w3r[1][0]) + __popc(A2_1 ^ w3r[1][1]);
            int nv1 = 2;
            if (wp < 15) {
                unsigned A3_0 = b2s[pbase + 4], A3_1 = b2s[pbase + 5];
                s1 += __popc(A3_0 ^ w3r[2][0]) + __popc(A3_1 ^ w3r[2][1]);
                nv1 = 3;
            }
            int e0 = mu * (64 * nv0 - 2 * s0);
            int e1 = mu * (64 * nv1 - 2 * s1);
            unsigned word = __ballot_sync(0xffffffffu, max(e0, e1) >= T);
            if (L == 0) b3s[pp * 4 + W] = word;
        }
    }
    __syncthreads();

    // ---- stage D: conv4 (128ch, cin 128, kh 6, no pad) ----
    {
        int c = tid;
        unsigned w4r[24];
#pragma unroll
        for (int k = 0; k < 24; k++) w4r[k] = g_wb4[c * 24 + k];
        int mu = g_mu4[c], T = g_T4[c];
        unsigned mask = 0;
        for (int w = 0; w < 16; w++) {
            int s = 0;
#pragma unroll
            for (int h = 0; h < 6; h++)
#pragma unroll
                for (int j = 0; j < 4; j++)
                    s += __popc(b3s[(h * 16 + w) * 4 + j] ^ w4r[h * 4 + j]);
            int d = 768 - 2 * s;
            mask |= (mu * d >= T) ? (1u << w) : 0u;
        }
        masks[c] = mask;
    }
    __syncthreads();
    // repack to fc bit order: k = c*16 + w; word j = masks[2j] | masks[2j+1]<<16
    if (tid < 64) fcb[tid] = masks[2 * tid] | (masks[2 * tid + 1] << 16);
    __syncthreads();

    // ---- stage E: fc (10 x 2048 binary dot) + bf (exact integer) ----
    for (int o = W; o < 10; o += 4) {
        int s = __popc(fcb[L]      ^ g_wfb[o * 64 + L])
              + __popc(fcb[L + 32] ^ g_wfb[o * 64 + 32 + L]);
        int tot = __reduce_add_sync(0xffffffffu, s);
        if (L == 0) out[(size_t)b * 10 + o] = (float)(2048 - 2 * tot) + bf[o];
    }
}

extern "C" void kernel_launch(void* const* d_in, const int* in_sizes, int n_in,
                              void* d_out, int out_size)
{
    const float* x   = (const float*)d_in[0];
    const float* w1  = (const float*)d_in[1];
    const float* b1  = (const float*)d_in[2];
    const float* w2  = (const float*)d_in[3];
    const float* b2  = (const float*)d_in[4];
    const float* w3  = (const float*)d_in[5];
    const float* b3  = (const float*)d_in[6];
    const float* w4  = (const float*)d_in[7];
    const float* b4  = (const float*)d_in[8];
    const float* g1  = (const float*)d_in[9];
    const float* be1 = (const float*)d_in[10];
    const float* m1  = (const float*)d_in[11];
    const float* v1  = (const float*)d_in[12];
    const float* g2  = (const float*)d_in[13];
    const float* be2 = (const float*)d_in[14];
    const float* m2  = (const float*)d_in[15];
    const float* v2  = (const float*)d_in[16];
    const float* g3  = (const float*)d_in[17];
    const float* be3 = (const float*)d_in[18];
    const float* m3  = (const float*)d_in[19];
    const float* v3  = (const float*)d_in[20];
    const float* g4  = (const float*)d_in[21];
    const float* be4 = (const float*)d_in[22];
    const float* m4  = (const float*)d_in[23];
    const float* v4  = (const float*)d_in[24];
    const float* wf  = (const float*)d_in[25];
    const float* bf  = (const float*)d_in[26];

    int B = in_sizes[0] / 768;

    prep_kernel<<<21, 256>>>(w1, b1, w2, b2, w3, b3, w4, b4,
                             g1, be1, m1, v1, g2, be2, m2, v2,
                             g3, be3, m3, v3, g4, be4, m4, v4, wf);
    bcnn_kernel<<<B, 128>>>(x, bf, (float*)d_out);
}

// round 7
// speedup vs baseline: 9.8733x; 1.0949x over previous
#include <cuda_runtime.h>
#include <cuda_bf16.h>
#include <cstdint>
#include <math.h>

// ---------------------------------------------------------------------------
// Binary CNN fully fused. Round 7: vectorized LDS (128/64-bit), sliding-window
// stage B, fully unrolled inner loops (compile-time boundaries).
// Numerics identical to round 6 (rel_err == 0.0).
// ---------------------------------------------------------------------------

#define EPSBND 1e-5
#define BAND   1e-3f

// preprocessed weights / params
__device__ float    g_w1s[32 * 9];            // sign(w1) as +-1.0f
__device__ double   g_inv1d[32], g_bz1d[32];  // exact BN params (double)
__device__ double   g_b1d[32];                // conv1 bias (double)
__device__ float    g_inv1f[32], g_off1f[32]; // fp32 fast path
__device__ unsigned g_wb2[64 * 3];            // [c*3+t], bit i = cin i
__device__ int      g_mu2[64],  g_T2[64];     // bit = (mu*d >= T)
__device__ unsigned g_wb3[128 * 3 * 2];       // [c*6 + 2t + j]
__device__ int      g_mu3[128], g_T3[128];
__device__ __align__(16) unsigned g_wb4[128 * 6 * 4];  // [c*24 + h*4 + j]
__device__ int      g_mu4[128], g_T4[128];
__device__ unsigned g_wfb[10 * 64];           // [o*64+jw]

__device__ __forceinline__ float bnref(float dv, float bias, float inv, float bz) {
    return __fadd_rn(__fmul_rn(__fadd_rn(dv, bias), inv), bz);
}

__device__ void mk_threshold(float b, float g, float be, float m, float v,
                             int* mu_out, int* T_out)
{
    float inv = __fmul_rn(g, rsqrtf(__fadd_rn(v, 1e-5f)));
    float bz  = __fsub_rn(be, __fmul_rn(m, inv));

    if (inv > 0.0f) {
        int lo = -1025, hi = 1025, ans = 1 << 20;
        while (lo <= hi) {
            int mid = lo + ((hi - lo) >> 1);
            if (bnref((float)mid, b, inv, bz) >= 0.0f) { ans = mid; hi = mid - 1; }
            else lo = mid + 1;
        }
        *mu_out = 1; *T_out = ans;
    } else if (inv < 0.0f) {
        int lo = -1025, hi = 1025, ans = -(1 << 20);
        while (lo <= hi) {
            int mid = lo + ((hi - lo) >> 1);
            if (bnref((float)mid, b, inv, bz) >= 0.0f) { ans = mid; lo = mid + 1; }
            else hi = mid - 1;
        }
        *mu_out = -1; *T_out = -ans;
    } else {
        *mu_out = 0; *T_out = (bz >= 0.0f) ? -(1 << 20) : (1 << 20);
    }
}

__global__ void prep_kernel(
    const float* __restrict__ w1, const float* __restrict__ b1,
    const float* __restrict__ w2, const float* __restrict__ b2,
    const float* __restrict__ w3, const float* __restrict__ b3,
    const float* __restrict__ w4, const float* __restrict__ b4,
    const float* __restrict__ g1, const float* __restrict__ be1,
    const float* __restrict__ m1, const float* __restrict__ v1,
    const float* __restrict__ g2, const float* __restrict__ be2,
    const float* __restrict__ m2, const float* __restrict__ v2,
    const float* __restrict__ g3, const float* __restrict__ be3,
    const float* __restrict__ m3, const float* __restrict__ v3,
    const float* __restrict__ g4, const float* __restrict__ be4,
    const float* __restrict__ m4, const float* __restrict__ v4,
    const float* __restrict__ wf)
{
    int u = blockIdx.x * blockDim.x + threadIdx.x;

    if (u < 288) {                       // sign(w1) as +-1.0f
        g_w1s[u] = (w1[u] >= 0.f) ? 1.f : -1.f;
        return;
    }
    u -= 288;
    if (u < 32) {                        // layer-1 BN params (double + fp32 fold)
        int c = u;
        double inv = (double)g1[c] / sqrt((double)v1[c] + EPSBND);
        double bz  = (double)be1[c] - (double)m1[c] * inv;
        g_inv1d[c] = inv;
        g_bz1d[c]  = bz;
        g_b1d[c]   = (double)b1[c];
        g_inv1f[c] = (float)inv;
        g_off1f[c] = (float)((double)b1[c] * inv + bz);
        return;
    }
    u -= 32;
    if (u < 320) {                       // integer thresholds, layers 2..4
        if (u < 64)       mk_threshold(b2[u], g2[u], be2[u], m2[u], v2[u],
                                       &g_mu2[u], &g_T2[u]);
        else if (u < 192) { int c = u - 64;
                          mk_threshold(b3[c], g3[c], be3[c], m3[c], v3[c],
                                       &g_mu3[c], &g_T3[c]); }
        else              { int c = u - 192;
                          mk_threshold(b4[c], g4[c], be4[c], m4[c], v4[c],
                                       &g_mu4[c], &g_T4[c]); }
        return;
    }
    u -= 320;
    if (u < 192) {                       // wb2: w2 (64,32,1,3)
        int c = u / 3, t = u % 3;
        unsigned word = 0;
        for (int i = 0; i < 32; i++)
            word |= (unsigned)(w2[c * 96 + i * 3 + t] >= 0.f) << i;
        g_wb2[u] = word;
        return;
    }
    u -= 192;
    if (u < 768) {                       // wb3: w3 (128,64,1,3)
        int c = u / 6, r = u % 6, t = r >> 1, j = r & 1;
        unsigned word = 0;
        for (int i = 0; i < 32; i++) {
            int cin = j * 32 + i;
            word |= (unsigned)(w3[c * 192 + cin * 3 + t] >= 0.f) << i;
        }
        g_wb3[u] = word;
        return;
    }
    u -= 768;
    if (u < 3072) {                      // wb4: w4 (128,128,6,1)
        int c = u / 24, r = u % 24, h = r >> 2, j = r & 3;
        unsigned word = 0;
        for (int i = 0; i < 32; i++) {
            int cin = j * 32 + i;
            word |= (unsigned)(w4[c * 768 + cin * 6 + h] >= 0.f) << i;
        }
        g_wb4[u] = word;
        return;
    }
    u -= 3072;
    if (u < 640) {                       // wfb: wf (10,2048), k = c*16+w
        int o = u / 64, jw = u % 64;
        unsigned word = 0;
        for (int i = 0; i < 32; i++)
            word |= (unsigned)(wf[o * 2048 + jw * 32 + i] >= 0.f) << i;
        g_wfb[u] = word;
    }
}

// ---------------------------------------------------------------------------
// Main fused kernel: 1 block = 1 sample, 128 threads (4 warps).
// ---------------------------------------------------------------------------
__global__ __launch_bounds__(128)
void bcnn_kernel(const float* __restrict__ x, const float* __restrict__ bf,
                 float* __restrict__ out)
{
    const int b   = blockIdx.x;
    const int tid = threadIdx.x;
    const int W   = tid >> 5;     // warp id
    const int L   = tid & 31;     // lane id

    __shared__ __align__(16) float    xs[6 * 136];   // [6][4 | 128 | 4] padded
    __shared__ __align__(16) unsigned b1s[192];
    __shared__ __align__(16) unsigned b2s[384];
    __shared__ __align__(16) unsigned b3s[384];
    __shared__ __align__(16) unsigned masks[128];
    __shared__ __align__(16) unsigned fcb[64];

    // load sample with zero padding (4 cols each side)
    const float* xb = x + (size_t)b * 768;
    for (int i = tid; i < 768; i += 128) {
        int r = i >> 7, c = i & 127;
        xs[r * 136 + 4 + c] = xb[i];
    }
    if (tid < 48) {
        int r = tid >> 3, j = tid & 7;
        xs[r * 136 + ((j < 4) ? j : (j + 128))] = 0.f;
    }

    // ---- stage A: conv1 + bias + bn + pool(w2) + binarize ----
    float wrf[9];
#pragma unroll
    for (int t = 0; t < 9; t++) wrf[t] = g_w1s[L * 9 + t];
    float invf = g_inv1f[L], offf = g_off1f[L];
    __syncthreads();

    for (int pos = W; pos < 192; pos += 4) {
        int h = pos >> 5, wp = pos & 31;
        const float4* rv = (const float4*)(xs + h * 136 + 4 * wp);
        float4 v0 = rv[0], v1 = rv[1], v2 = rv[2];
        float xv[12] = {v0.x, v0.y, v0.z, v0.w,
                        v1.x, v1.y, v1.z, v1.w,
                        v2.x, v2.y, v2.z, v2.w};
        float s0 = 0.f, s1 = 0.f;
#pragma unroll
        for (int t = 0; t < 9; t++) {
            s0 = __fmaf_rn(wrf[t], xv[t],     s0);
            s1 = __fmaf_rn(wrf[t], xv[t + 2], s1);
        }
        float ym = fmaxf(__fmaf_rn(s0, invf, offf), __fmaf_rn(s1, invf, offf));
        bool bit;
        if (fabsf(ym) >= BAND) {
            bit = (ym >= 0.f);
        } else {                        // rare exact fallback (double, round-5 chain)
            double inv1 = g_inv1d[L], bz1 = g_bz1d[L], bb1 = g_b1d[L];
            double s0d = 0.0, s1d = 0.0;
#pragma unroll
            for (int t = 0; t < 9; t++) {
                s0d = fma((double)wrf[t], (double)xv[t],     s0d);
                s1d = fma((double)wrf[t], (double)xv[t + 2], s1d);
            }
            double y0 = (s0d + bb1) * inv1 + bz1;
            double y1 = (s1d + bb1) * inv1 + bz1;
            bit = (y0 >= 0.0) || (y1 >= 0.0);
        }
        unsigned word = __ballot_sync(0xffffffffu, bit);
        if (L == 0) b1s[pos] = word;
    }
    __syncthreads();

    // ---- stage B: conv2 (64ch, cin 32, kw 3, pad 1), sliding window ----
    {
        int q = W & 1;                 // channel half, c = q*32 + L
        int c = q * 32 + L;
        unsigned wt0 = g_wb2[c * 3 + 0];
        unsigned wt1 = g_wb2[c * 3 + 1];
        unsigned wt2 = g_wb2[c * 3 + 2];
        int mu = g_mu2[c], T = g_T2[c];
        int r0 = 3 * (W >> 1);         // pair 0: rows 0-2, pair 1: rows 3-5
        for (int r = r0; r < r0 + 3; r++) {
            const unsigned* rp = b1s + r * 32;
            unsigned Acur = rp[0], Anext = rp[1];
            {   // w = 0 (2 valid taps)
                int s = __popc(Acur ^ wt1) + __popc(Anext ^ wt2);
                unsigned word = __ballot_sync(0xffffffffu, mu * (64 - 2 * s) >= T);
                if (L == 0) b2s[r * 64 + q] = word;
            }
#pragma unroll
            for (int w = 1; w <= 30; w++) {
                unsigned Aprev = Acur; Acur = Anext; Anext = rp[w + 1];
                int s = __popc(Aprev ^ wt0) + __popc(Acur ^ wt1)
                      + __popc(Anext ^ wt2);
                unsigned word = __ballot_sync(0xffffffffu, mu * (96 - 2 * s) >= T);
                if (L == 0) b2s[r * 64 + 2 * w + q] = word;
            }
            {   // w = 31 (2 valid taps)
                int s = __popc(Acur ^ wt0) + __popc(Anext ^ wt1);
                unsigned word = __ballot_sync(0xffffffffu, mu * (64 - 2 * s) >= T);
                if (L == 0) b2s[r * 64 + 62 + q] = word;
            }
        }
    }
    __syncthreads();

    // ---- stage C: conv3 (128ch, cin 64, kw 3, pad 1) + pool(w2) ----
    {
        int c = tid;                   // warp W owns channels 32W..32W+31
        unsigned w00 = g_wb3[c * 6 + 0], w01 = g_wb3[c * 6 + 1];
        unsigned w10 = g_wb3[c * 6 + 2], w11 = g_wb3[c * 6 + 3];
        unsigned w20 = g_wb3[c * 6 + 4], w21 = g_wb3[c * 6 + 5];
        int mu = g_mu3[c], T = g_T3[c];

        for (int h = 0; h < 6; h++) {
            const unsigned* rp = b2s + h * 64;
#pragma unroll
            for (int wp = 0; wp < 16; wp++) {
                uint4 M = *(const uint4*)(rp + 4 * wp);   // A(2wp), A(2wp+1)
                int s0 = __popc(M.x ^ w10) + __popc(M.y ^ w11)
                       + __popc(M.z ^ w20) + __popc(M.w ^ w21);
                int s1 = __popc(M.x ^ w00) + __popc(M.y ^ w01)
                       + __popc(M.z ^ w10) + __popc(M.w ^ w11);
                int d0, d1;
                if (wp > 0) {
                    uint2 P = *(const uint2*)(rp + 4 * wp - 2); // A(2wp-1)
                    s0 += __popc(P.x ^ w00) + __popc(P.y ^ w01);
                    d0 = 192 - 2 * s0;
                } else d0 = 128 - 2 * s0;
                if (wp < 15) {
                    uint2 N = *(const uint2*)(rp + 4 * wp + 4); // A(2wp+2)
                    s1 += __popc(N.x ^ w20) + __popc(N.y ^ w21);
                    d1 = 192 - 2 * s1;
                } else d1 = 128 - 2 * s1;
                int e0 = mu * d0, e1 = mu * d1;
                unsigned word = __ballot_sync(0xffffffffu, max(e0, e1) >= T);
                if (L == 0) b3s[(h * 16 + wp) * 4 + W] = word;
            }
        }
    }
    __syncthreads();

    // ---- stage D: conv4 (128ch, cin 128, kh 6, no pad) ----
    {
        int c = tid;
        uint4 wv[6];
#pragma unroll
        for (int h = 0; h < 6; h++)
            wv[h] = *(const uint4*)&g_wb4[c * 24 + h * 4];
        int mu = g_mu4[c], T = g_T4[c];
        unsigned mask = 0;
#pragma unroll 4
        for (int w = 0; w < 16; w++) {
            int s = 0;
#pragma unroll
            for (int h = 0; h < 6; h++) {
                uint4 A = *(const uint4*)&b3s[(h * 16 + w) * 4];
                s += __popc(A.x ^ wv[h].x) + __popc(A.y ^ wv[h].y)
                   + __popc(A.z ^ wv[h].z) + __popc(A.w ^ wv[h].w);
            }
            mask |= (mu * (768 - 2 * s) >= T) ? (1u << w) : 0u;
        }
        masks[c] = mask;
    }
    __syncthreads();
    // repack to fc bit order: k = c*16 + w; word j = masks[2j] | masks[2j+1]<<16
    if (tid < 64) fcb[tid] = masks[2 * tid] | (masks[2 * tid + 1] << 16);
    __syncthreads();

    // ---- stage E: fc (10 x 2048 binary dot) + bf (exact integer) ----
    for (int o = W; o < 10; o += 4) {
        int s = __popc(fcb[L]      ^ g_wfb[o * 64 + L])
              + __popc(fcb[L + 32] ^ g_wfb[o * 64 + 32 + L]);
        int tot = __reduce_add_sync(0xffffffffu, s);
        if (L == 0) out[(size_t)b * 10 + o] = (float)(2048 - 2 * tot) + bf[o];
    }
}

extern "C" void kernel_launch(void* const* d_in, const int* in_sizes, int n_in,
                              void* d_out, int out_size)
{
    const float* x   = (const float*)d_in[0];
    const float* w1  = (const float*)d_in[1];
    const float* b1  = (const float*)d_in[2];
    const float* w2  = (const float*)d_in[3];
    const float* b2  = (const float*)d_in[4];
    const float* w3  = (const float*)d_in[5];
    const float* b3  = (const float*)d_in[6];
    const float* w4  = (const float*)d_in[7];
    const float* b4  = (const float*)d_in[8];
    const float* g1  = (const float*)d_in[9];
    const float* be1 = (const float*)d_in[10];
    const float* m1  = (const float*)d_in[11];
    const float* v1  = (const float*)d_in[12];
    const float* g2  = (const float*)d_in[13];
    const float* be2 = (const float*)d_in[14];
    const float* m2  = (const float*)d_in[15];
    const float* v2  = (const float*)d_in[16];
    const float* g3  = (const float*)d_in[17];
    const float* be3 = (const float*)d_in[18];
    const float* m3  = (const float*)d_in[19];
    const float* v3  = (const float*)d_in[20];
    const float* g4  = (const float*)d_in[21];
    const float* be4 = (const float*)d_in[22];
    const float* m4  = (const float*)d_in[23];
    const float* v4  = (const float*)d_in[24];
    const float* wf  = (const float*)d_in[25];
    const float* bf  = (const float*)d_in[26];

    int B = in_sizes[0] / 768;

    prep_kernel<<<21, 256>>>(w1, b1, w2, b2, w3, b3, w4, b4,
                             g1, be1, m1, v1, g2, be2, m2, v2,
                             g3, be3, m3, v3, g4, be4, m4, v4, wf);
    bcnn_kernel<<<B, 128>>>(x, bf, (float*)d_out);
}